// round 11
// baseline (speedup 1.0000x reference)
#include <cuda_runtime.h>
#include <cuda_bf16.h>
#include <math.h>
#include <stdint.h>

#define N_ROWS 4096
#define D      256
#define TWO_N  8192
#define BM 128
#define BN 128
#define BK 32
#define NKT (D / BK)              // 8 k-chunks
#define NCOLTILES 64
#define NLOSSBLK 256              // 16 rows per block
#define NTILES 1552
#define GRID_GEMM 296             // 2 CTAs per SM, persistent

// exp(x/T) = 2^(x * invT * log2(e))
__device__ __constant__ float c_l2T  = 20.609929f;
__device__ __constant__ float c_invT = 14.285714285714286f;

// Scratch (device globals; no allocation anywhere)
__device__ __nv_bfloat16  g_hi[TWO_N * D];       // bf16 normalized
__device__ float          g_partial[N_ROWS * NCOLTILES];
__device__ float          g_blocksum[NLOSSBLK];
__device__ int            g_counter = 0;         // loss last-block counter
__device__ int            g_tileCtr = 0;         // GEMM work-steal counter

// ---------------------------------------------------------------------------
// PTX helpers (sm_80+ baseline only)
// ---------------------------------------------------------------------------
__device__ __forceinline__ uint32_t smem_to_u32(const void* p) {
    uint32_t a;
    asm("{ .reg .u64 t; cvta.to.shared.u64 t, %1; cvt.u32.u64 %0, t; }" : "=r"(a) : "l"(p));
    return a;
}
__device__ __forceinline__ float ex2(float x) {
    float r;
    asm("ex2.approx.ftz.f32 %0, %1;" : "=f"(r) : "f"(x));
    return r;
}
#define CP_ASYNC16(dst, src) \
    asm volatile("cp.async.cg.shared.global [%0], [%1], 16;" :: "r"(dst), "l"(src))
#define CP_COMMIT() asm volatile("cp.async.commit_group;" ::: "memory")
#define CP_WAIT(n)  asm volatile("cp.async.wait_group %0;" :: "n"(n) : "memory")

__device__ __forceinline__ void ldsm4(uint32_t* r, uint32_t addr) {
    asm volatile("ldmatrix.sync.aligned.m8n8.x4.shared.b16 {%0,%1,%2,%3}, [%4];"
        : "=r"(r[0]), "=r"(r[1]), "=r"(r[2]), "=r"(r[3]) : "r"(addr));
}
__device__ __forceinline__ void mma16816(float* c, const uint32_t* a,
                                         uint32_t b0, uint32_t b1) {
    asm volatile("mma.sync.aligned.m16n8k16.row.col.f32.bf16.bf16.f32 "
        "{%0,%1,%2,%3}, {%4,%5,%6,%7}, {%8,%9}, {%0,%1,%2,%3};"
        : "+f"(c[0]), "+f"(c[1]), "+f"(c[2]), "+f"(c[3])
        : "r"(a[0]), "r"(a[1]), "r"(a[2]), "r"(a[3]), "r"(b0), "r"(b1));
}

// Stage: 128 rows x 128B (8x16B chunks). Chunks 0-3 = A, 4-7 = B.
// XOR swizzle: slot = ch ^ (row & 7) -> conflict-free ldmatrix.
__device__ __forceinline__ uint32_t swadr(uint32_t base, int rowByte, int rm, int ch) {
    return base + rowByte + ((ch ^ rm) << 4);
}

#define STAGE_BYTES 16384
#define SCRATCH_OFF (2 * STAGE_BYTES)            // 32768: dedicated epilogue scratch
#define SMEM_TOTAL  (SCRATCH_OFF + 3072)         // 35840 B

// ---------------------------------------------------------------------------
// Kernel 1: L2-normalize rows -> g_hi (bf16). TWO rows per warp (the two
// shuffle-reduction chains interleave, halving exposed latency). Grid 512.
// ---------------------------------------------------------------------------
__global__ void __launch_bounds__(256) normalize_kernel(const float* __restrict__ z1,
                                                        const float* __restrict__ z2) {
    const int wid  = blockIdx.x * 8 + (threadIdx.x >> 5);
    const int lane = threadIdx.x & 31;
    const int row0 = wid * 2, row1 = row0 + 1;

    const float* s0 = (row0 < N_ROWS) ? (z1 + (size_t)row0 * D)
                                      : (z2 + (size_t)(row0 - N_ROWS) * D);
    const float* s1 = (row1 < N_ROWS) ? (z1 + (size_t)row1 * D)
                                      : (z2 + (size_t)(row1 - N_ROWS) * D);

    float4 a0 = reinterpret_cast<const float4*>(s0)[lane];
    float4 b0 = reinterpret_cast<const float4*>(s0)[lane + 32];
    float4 a1 = reinterpret_cast<const float4*>(s1)[lane];
    float4 b1 = reinterpret_cast<const float4*>(s1)[lane + 32];

    float ss0 = a0.x*a0.x + a0.y*a0.y + a0.z*a0.z + a0.w*a0.w
              + b0.x*b0.x + b0.y*b0.y + b0.z*b0.z + b0.w*b0.w;
    float ss1 = a1.x*a1.x + a1.y*a1.y + a1.z*a1.z + a1.w*a1.w
              + b1.x*b1.x + b1.y*b1.y + b1.z*b1.z + b1.w*b1.w;
    #pragma unroll
    for (int off = 16; off > 0; off >>= 1) {
        ss0 += __shfl_xor_sync(0xffffffffu, ss0, off);
        ss1 += __shfl_xor_sync(0xffffffffu, ss1, off);
    }
    const float sc0 = 1.0f / fmaxf(sqrtf(ss0), 1e-12f);
    const float sc1 = 1.0f / fmaxf(sqrtf(ss1), 1e-12f);

    __nv_bfloat162* d0 = reinterpret_cast<__nv_bfloat162*>(g_hi + (size_t)row0 * D);
    __nv_bfloat162* d1 = reinterpret_cast<__nv_bfloat162*>(g_hi + (size_t)row1 * D);
    d0[lane * 2 + 0]        = __halves2bfloat162(__float2bfloat16(a0.x*sc0), __float2bfloat16(a0.y*sc0));
    d0[lane * 2 + 1]        = __halves2bfloat162(__float2bfloat16(a0.z*sc0), __float2bfloat16(a0.w*sc0));
    d0[(lane + 32) * 2 + 0] = __halves2bfloat162(__float2bfloat16(b0.x*sc0), __float2bfloat16(b0.y*sc0));
    d0[(lane + 32) * 2 + 1] = __halves2bfloat162(__float2bfloat16(b0.z*sc0), __float2bfloat16(b0.w*sc0));
    d1[lane * 2 + 0]        = __halves2bfloat162(__float2bfloat16(a1.x*sc1), __float2bfloat16(a1.y*sc1));
    d1[lane * 2 + 1]        = __halves2bfloat162(__float2bfloat16(a1.z*sc1), __float2bfloat16(a1.w*sc1));
    d1[(lane + 32) * 2 + 0] = __halves2bfloat162(__float2bfloat16(b1.x*sc1), __float2bfloat16(b1.y*sc1));
    d1[(lane + 32) * 2 + 1] = __halves2bfloat162(__float2bfloat16(b1.z*sc1), __float2bfloat16(b1.w*sc1));
}

// ---------------------------------------------------------------------------
// Stage loader: A 128x32 (chunks 0-3) + B 128x32 (chunks 4-7) = 1024 16B chunks
// ---------------------------------------------------------------------------
__device__ __forceinline__ void load_stage(uint32_t stageAddr, int kt,
                                           int rowBase, int colBase, int tid) {
    const int kOff = kt * BK;
    #pragma unroll
    for (int i = 0; i < 4; i++) {
        const int v = i * 256 + tid;
        const int row = v >> 3, ch = v & 7;       // ch 0-3: A, 4-7: B
        const int gRow = (ch < 4) ? (rowBase + row) : (colBase + row);
        const void* src = g_hi + (size_t)gRow * D + kOff + (ch & 3) * 8;
        const uint32_t dst = stageAddr + row * 128 + ((ch ^ (row & 7)) << 4);
        CP_ASYNC16(dst, src);
    }
}

// Tile decode: b<1024 -> right half (bx=b>>5, ct=32+(b&31)); else triangular.
__device__ __forceinline__ void decode_tile(int b, int& bx, int& ct, bool& sym) {
    if (b < 1024) {
        bx = b >> 5; ct = 32 + (b & 31); sym = false;
    } else {
        const int t = b - 1024;
        int e = (int)((sqrtf(8.0f * t + 1.0f) - 1.0f) * 0.5f);
        while ((e + 1) * (e + 2) / 2 <= t) e++;
        while (e * (e + 1) / 2 > t) e--;
        bx = e; ct = t - e * (e + 1) / 2; sym = (ct != bx);
    }
}

// ---------------------------------------------------------------------------
// Kernel 2: persistent HMMA fused sim-GEMM + exp + row/col sums.
// R7 pipeline (BK=32, 2-stage, 2 syncs/chunk, cross-tile prefetch) +
// ONE-TILE-AHEAD work stealing: the next tile's index is grabbed during the
// PREVIOUS tile and published by existing syncs, so ALL decode stays outside
// the kt-loop (register-pressure discipline; cf. R9 failure).
// ---------------------------------------------------------------------------
__global__ void __launch_bounds__(256, 2) simsum_mma_kernel() {
    extern __shared__ char smem[];
    const uint32_t smem_u32 = smem_to_u32(smem);
    const int tid = threadIdx.x;

    __shared__ int sh_next;

    const int lane  = tid & 31;
    const int w     = tid >> 5;
    const int warpM = w >> 1;
    const int warpN = w & 1;

    const int aRow  = warpM * 32 + (lane & 7) + ((lane >> 3) & 1) * 8;
    const int aCh   = (lane >> 4) & 1;
    const int aRm   = aRow & 7;
    const int bRow  = warpN * 64 + (lane & 7) + ((lane >> 4) & 1) * 8;
    const int bCh   = (lane >> 3) & 1;
    const int bRm   = bRow & 7;
    const int aRowByte[2] = {aRow * 128, (aRow + 16) * 128};
    const int bRowByte[4] = {bRow * 128, (bRow + 16) * 128,
                             (bRow + 32) * 128, (bRow + 48) * 128};

    float* rowScratch = reinterpret_cast<float*>(smem + SCRATCH_OFF);        // [2][128]
    float* colScratch = reinterpret_cast<float*>(smem + SCRATCH_OFF) + 256;  // [2][4][64]

    // Grab first tile, then pre-grab the second (one-ahead pipeline).
    if (tid == 0) sh_next = atomicAdd(&g_tileCtr, 1);
    __syncthreads();
    int tile = sh_next;
    __syncthreads();                 // all reads done before rewrite
    if (tid == 0) sh_next = atomicAdd(&g_tileCtr, 1);
    __syncthreads();
    int nxt = sh_next;
    // grid 296 << NTILES so tile < NTILES always holds here

    int bx, colTile; bool sym;
    decode_tile(tile, bx, colTile, sym);
    int rowBase = bx * BM, colBase = colTile * BN;

    int chunk = 0;                 // global chunk parity counter
    load_stage(smem_u32, 0, rowBase, colBase, tid);
    CP_COMMIT();

    #pragma unroll 1
    while (true) {
        // Next tile fully decoded OUTSIDE the kt-loop.
        const bool hasNext = (nxt < NTILES);
        int nbx = 0, nct = 0; bool nsym = false;
        if (hasNext) decode_tile(nxt, nbx, nct, nsym);
        const int nRowBase = nbx * BM, nColBase = nct * BN;

        float acc[2][8][4];
        #pragma unroll
        for (int mt = 0; mt < 2; mt++)
            #pragma unroll
            for (int nt = 0; nt < 8; nt++)
                #pragma unroll
                for (int r = 0; r < 4; r++) acc[mt][nt][r] = 0.0f;

        #pragma unroll 1
        for (int kt = 0; kt < NKT; kt++) {
            const uint32_t stage  = smem_u32 + (uint32_t)(chunk & 1) * STAGE_BYTES;
            const uint32_t nstage = smem_u32 + (uint32_t)((chunk + 1) & 1) * STAGE_BYTES;
            if (kt + 1 < NKT) {
                load_stage(nstage, kt + 1, rowBase, colBase, tid);
                CP_COMMIT(); CP_WAIT(1);
            } else if (hasNext) {
                load_stage(nstage, 0, nRowBase, nColBase, tid);
                CP_COMMIT(); CP_WAIT(1);
            } else {
                CP_WAIT(0);
            }
            __syncthreads();

            #pragma unroll
            for (int s = 0; s < 2; s++) {
                uint32_t ah[2][4], bh[4][4];
                #pragma unroll
                for (int mt = 0; mt < 2; mt++)
                    ldsm4(ah[mt], swadr(stage, aRowByte[mt], aRm, 2 * s + aCh));
                #pragma unroll
                for (int p = 0; p < 4; p++)
                    ldsm4(bh[p], swadr(stage, bRowByte[p], bRm, 4 + 2 * s + bCh));
                #pragma unroll
                for (int mt = 0; mt < 2; mt++)
                    #pragma unroll
                    for (int nt = 0; nt < 8; nt++)
                        mma16816(acc[mt][nt], ah[mt], bh[nt >> 1][(nt & 1) * 2],
                                 bh[nt >> 1][(nt & 1) * 2 + 1]);
            }
            __syncthreads();
            chunk++;
        }

        // ---------------- Epilogue (next tile's kt0 load is in flight) -------
        const float l2T = c_l2T;
        float rs0[2] = {0.0f, 0.0f}, rs1[2] = {0.0f, 0.0f};
        float cs[16];
        #pragma unroll
        for (int i = 0; i < 16; i++) cs[i] = 0.0f;

        #pragma unroll
        for (int mt = 0; mt < 2; mt++)
            #pragma unroll
            for (int nt = 0; nt < 8; nt++) {
                const float e0 = ex2(acc[mt][nt][0] * l2T);
                const float e1 = ex2(acc[mt][nt][1] * l2T);
                const float e2 = ex2(acc[mt][nt][2] * l2T);
                const float e3 = ex2(acc[mt][nt][3] * l2T);
                rs0[mt] += e0 + e1;
                rs1[mt] += e2 + e3;
                cs[nt * 2 + 0] += e0 + e2;
                cs[nt * 2 + 1] += e1 + e3;
            }

        #pragma unroll
        for (int off = 1; off <= 2; off <<= 1) {
            #pragma unroll
            for (int mt = 0; mt < 2; mt++) {
                rs0[mt] += __shfl_xor_sync(0xffffffffu, rs0[mt], off);
                rs1[mt] += __shfl_xor_sync(0xffffffffu, rs1[mt], off);
            }
        }
        if ((lane & 3) == 0) {
            const int r8 = lane >> 2;
            #pragma unroll
            for (int mt = 0; mt < 2; mt++) {
                rowScratch[warpN * 128 + warpM * 32 + mt * 16 + 0 + r8] = rs0[mt];
                rowScratch[warpN * 128 + warpM * 32 + mt * 16 + 8 + r8] = rs1[mt];
            }
        }
        if (sym) {
            #pragma unroll
            for (int i = 0; i < 16; i++) {
                #pragma unroll
                for (int off = 4; off <= 16; off <<= 1)
                    cs[i] += __shfl_xor_sync(0xffffffffu, cs[i], off);
            }
            if (lane < 4) {
                #pragma unroll
                for (int nt = 0; nt < 8; nt++) {
                    colScratch[(warpN * 4 + warpM) * 64 + nt * 8 + lane * 2 + 0] = cs[nt * 2 + 0];
                    colScratch[(warpN * 4 + warpM) * 64 + nt * 8 + lane * 2 + 1] = cs[nt * 2 + 1];
                }
            }
        }
        __syncthreads();

        if (tid < 128) {
            const float p = rowScratch[tid] + rowScratch[128 + tid];
            g_partial[(size_t)(rowBase + tid) * NCOLTILES + colTile] = p;
            if (sym) {
                const int wn = tid >> 6, ix = tid & 63;
                float c = colScratch[(wn * 4 + 0) * 64 + ix] + colScratch[(wn * 4 + 1) * 64 + ix]
                        + colScratch[(wn * 4 + 2) * 64 + ix] + colScratch[(wn * 4 + 3) * 64 + ix];
                g_partial[(size_t)(colBase + tid) * NCOLTILES + bx] = c;
            }
        }
        // Pre-grab the tile AFTER next; published by the sync below.
        if (tid == 0 && hasNext) sh_next = atomicAdd(&g_tileCtr, 1);
        __syncthreads();   // scratch reuse safety + sh_next publication

        if (!hasNext) break;
        tile = nxt; bx = nbx; colTile = nct; sym = nsym;
        rowBase = nRowBase; colBase = nColBase;
        nxt = sh_next;     // the newly grabbed one-ahead tile
    }
}

// ---------------------------------------------------------------------------
// Kernel 3: per-row loss + grid-wide mean (last-block pattern, deterministic).
// 512 threads, 16 rows per block -> 256 blocks.
// ---------------------------------------------------------------------------
__global__ void __launch_bounds__(512) loss_reduce_kernel(float* __restrict__ out) {
    __shared__ float warpLoss[16];
    __shared__ int   isLast;
    const int bid  = blockIdx.x;
    const int row  = bid * 16 + (threadIdx.x >> 5);
    const int lane = threadIdx.x & 31;

    float total = g_partial[(size_t)row * NCOLTILES + lane]
                + g_partial[(size_t)row * NCOLTILES + lane + 32];

    const uint4 va = reinterpret_cast<const uint4*>(g_hi + (size_t)row * D)[lane];
    const uint4 vb = reinterpret_cast<const uint4*>(g_hi + (size_t)(N_ROWS + row) * D)[lane];
    const uint4 vc = reinterpret_cast<const uint4*>(g_hi + (size_t)N_ROWS * D)[lane];

    float dp = 0.0f, d0 = 0.0f;
    {
        const __nv_bfloat162* pa = reinterpret_cast<const __nv_bfloat162*>(&va);
        const __nv_bfloat162* pb = reinterpret_cast<const __nv_bfloat162*>(&vb);
        const __nv_bfloat162* pc = reinterpret_cast<const __nv_bfloat162*>(&vc);
        #pragma unroll
        for (int i = 0; i < 4; i++) {
            float2 fa = __bfloat1622float2(pa[i]);
            float2 fb = __bfloat1622float2(pb[i]);
            float2 fc = __bfloat1622float2(pc[i]);
            dp += fa.x * fb.x + fa.y * fb.y;
            d0 += fa.x * fc.x + fa.y * fc.y;
        }
    }
    #pragma unroll
    for (int off = 16; off > 0; off >>= 1) {
        total += __shfl_xor_sync(0xffffffffu, total, off);
        dp    += __shfl_xor_sync(0xffffffffu, dp, off);
        d0    += __shfl_xor_sync(0xffffffffu, d0, off);
    }
    if (lane == 0) {
        float sum_negs = total - ex2(d0 * c_l2T);
        warpLoss[threadIdx.x >> 5] = logf(sum_negs) - dp * c_invT;
    }
    __syncthreads();

    if (threadIdx.x == 0) {
        float bs = 0.0f;
        #pragma unroll
        for (int i = 0; i < 16; i++) bs += warpLoss[i];
        g_blocksum[bid] = bs;
        __threadfence();
        int old = atomicAdd(&g_counter, 1);
        isLast = (old == NLOSSBLK - 1);
    }
    __syncthreads();

    if (isLast) {
        __shared__ float s[512];
        float v = 0.0f;
        if (threadIdx.x < NLOSSBLK) {
            asm volatile("ld.global.cg.f32 %0, [%1];" : "=f"(v)
                         : "l"(g_blocksum + threadIdx.x));
        }
        s[threadIdx.x] = v;
        __syncthreads();
        #pragma unroll
        for (int stride = 256; stride > 0; stride >>= 1) {
            if (threadIdx.x < stride) s[threadIdx.x] += s[threadIdx.x + stride];
            __syncthreads();
        }
        if (threadIdx.x == 0) {
            out[0] = s[0] * (1.0f / N_ROWS);
            g_counter = 0;   // reset for graph replay
            g_tileCtr = 0;   // reset work-steal counter for graph replay
        }
    }
}

// ---------------------------------------------------------------------------
extern "C" void kernel_launch(void* const* d_in, const int* in_sizes, int n_in,
                              void* d_out, int out_size) {
    const float* z1 = (const float*)d_in[0];
    const float* z2 = (const float*)d_in[1];
    float* out = (float*)d_out;

    cudaFuncSetAttribute(simsum_mma_kernel,
                         cudaFuncAttributeMaxDynamicSharedMemorySize, SMEM_TOTAL);

    normalize_kernel<<<TWO_N / 16, 256>>>(z1, z2);
    simsum_mma_kernel<<<GRID_GEMM, 256, SMEM_TOTAL>>>();
    loss_reduce_kernel<<<NLOSSBLK, 512>>>(out);
}

// round 12
// speedup vs baseline: 1.8909x; 1.8909x over previous
#include <cuda_runtime.h>
#include <cuda_bf16.h>
#include <math.h>
#include <stdint.h>

#define N_ROWS 4096
#define D      256
#define TWO_N  8192
#define BM 128
#define BN 128
#define BK 128                     // int8 elements per k-chunk (128 bytes/row)
#define NKT (D / BK)               // 2 k-chunks
#define NCOLTILES 64
#define NLOSSBLK (N_ROWS / 8)      // 512 loss blocks
#define NTILES 1552
#define GRID_GEMM 296              // 2 CTAs per SM, persistent

// exp(x/T) = 2^(x * invT * log2(e))
__device__ __constant__ float c_l2T  = 20.609929f;
__device__ __constant__ float c_invT = 14.285714285714286f;

// Scratch (device globals; no allocation anywhere)
__device__ int8_t  g_q[TWO_N * D];       // int8 quantized normalized rows
__device__ float   g_rs[TWO_N];          // per-row dequant scale (absmax/127)
__device__ float   g_partial[N_ROWS * NCOLTILES];
__device__ float   g_blocksum[NLOSSBLK];
__device__ int     g_counter = 0;        // loss last-block counter

// ---------------------------------------------------------------------------
// PTX helpers (sm_80+ baseline only)
// ---------------------------------------------------------------------------
__device__ __forceinline__ uint32_t smem_to_u32(const void* p) {
    uint32_t a;
    asm("{ .reg .u64 t; cvta.to.shared.u64 t, %1; cvt.u32.u64 %0, t; }" : "=r"(a) : "l"(p));
    return a;
}
__device__ __forceinline__ float ex2(float x) {
    float r;
    asm("ex2.approx.ftz.f32 %0, %1;" : "=f"(r) : "f"(x));
    return r;
}
#define CP_ASYNC16(dst, src) \
    asm volatile("cp.async.cg.shared.global [%0], [%1], 16;" :: "r"(dst), "l"(src))
#define CP_COMMIT() asm volatile("cp.async.commit_group;" ::: "memory")
#define CP_WAIT(n)  asm volatile("cp.async.wait_group %0;" :: "n"(n) : "memory")

__device__ __forceinline__ void ldsm4(uint32_t* r, uint32_t addr) {
    asm volatile("ldmatrix.sync.aligned.m8n8.x4.shared.b16 {%0,%1,%2,%3}, [%4];"
        : "=r"(r[0]), "=r"(r[1]), "=r"(r[2]), "=r"(r[3]) : "r"(addr));
}
// s8 IMMA: D(s32) = A(s8 16x32) * B(s8 32x8) + D
__device__ __forceinline__ void imma16832(int* c, const uint32_t* a,
                                          uint32_t b0, uint32_t b1) {
    asm volatile("mma.sync.aligned.m16n8k32.row.col.s32.s8.s8.s32 "
        "{%0,%1,%2,%3}, {%4,%5,%6,%7}, {%8,%9}, {%0,%1,%2,%3};"
        : "+r"(c[0]), "+r"(c[1]), "+r"(c[2]), "+r"(c[3])
        : "r"(a[0]), "r"(a[1]), "r"(a[2]), "r"(a[3]), "r"(b0), "r"(b1));
}

// Stage (32 KB): A region 128 rows x 128B (k-chunk of 128 int8) at +0,
// B region same at +16384. Full 3-bit XOR swizzle: slot = ch ^ (row & 7).
__device__ __forceinline__ uint32_t swadr(uint32_t base, int rowByte, int rm, int ch) {
    return base + rowByte + ((ch ^ rm) << 4);
}

#define STAGE_BYTES 32768
#define SCRATCH_OFF (2 * STAGE_BYTES)            // 65536: epilogue scratch
#define SMEM_TOTAL  (SCRATCH_OFF + 3072)         // 68608 B (2 CTAs/SM fits)

// ---------------------------------------------------------------------------
// Kernel 1: L2-normalize rows -> int8 (per-row absmax quant) + scale.
// One warp per row.
// ---------------------------------------------------------------------------
__global__ void __launch_bounds__(256) normalize_kernel(const float* __restrict__ z1,
                                                        const float* __restrict__ z2) {
    const int row  = blockIdx.x * 8 + (threadIdx.x >> 5);
    const int lane = threadIdx.x & 31;
    const float* src = (row < N_ROWS) ? (z1 + (size_t)row * D)
                                      : (z2 + (size_t)(row - N_ROWS) * D);
    float4 a = reinterpret_cast<const float4*>(src)[lane];
    float4 b = reinterpret_cast<const float4*>(src)[lane + 32];
    float ss = a.x*a.x + a.y*a.y + a.z*a.z + a.w*a.w
             + b.x*b.x + b.y*b.y + b.z*b.z + b.w*b.w;
    #pragma unroll
    for (int off = 16; off > 0; off >>= 1)
        ss += __shfl_xor_sync(0xffffffffu, ss, off);
    const float scale = 1.0f / fmaxf(sqrtf(ss), 1e-12f);

    float v[8] = {a.x*scale, a.y*scale, a.z*scale, a.w*scale,
                  b.x*scale, b.y*scale, b.z*scale, b.w*scale};
    float m = 0.0f;
    #pragma unroll
    for (int i = 0; i < 8; i++) m = fmaxf(m, fabsf(v[i]));
    #pragma unroll
    for (int off = 16; off > 0; off >>= 1)
        m = fmaxf(m, __shfl_xor_sync(0xffffffffu, m, off));

    const float qs = 127.0f / m;
    int q[8];
    #pragma unroll
    for (int i = 0; i < 8; i++) q[i] = __float2int_rn(v[i] * qs);

    uint32_t w0 = (q[0] & 255) | ((q[1] & 255) << 8) | ((q[2] & 255) << 16) | (q[3] << 24);
    uint32_t w1 = (q[4] & 255) | ((q[5] & 255) << 8) | ((q[6] & 255) << 16) | (q[7] << 24);
    uint32_t* dst = reinterpret_cast<uint32_t*>(g_q + (size_t)row * D);
    dst[lane]      = w0;        // elements 4*lane .. 4*lane+3
    dst[lane + 32] = w1;        // elements 128+4*lane ..
    if (lane == 0) g_rs[row] = m * (1.0f / 127.0f);
}

// ---------------------------------------------------------------------------
// Stage loader: A 128x128B (region 0) + B 128x128B (region +16384).
// 2048 16B chunks, 8 per thread.
// ---------------------------------------------------------------------------
__device__ __forceinline__ void load_stage(uint32_t stageAddr, int kt,
                                           int rowBase, int colBase, int tid) {
    const int kOff = kt * BK;
    #pragma unroll
    for (int i = 0; i < 8; i++) {
        const int v = i * 256 + tid;              // 0..2047
        const int half = v >> 10;                 // 0 = A, 1 = B
        const int r = (v >> 3) & 127, c = v & 7;
        const int gRow = half ? (colBase + r) : (rowBase + r);
        const void* src = g_q + (size_t)gRow * D + kOff + c * 16;
        const uint32_t dst = stageAddr + half * 16384 + r * 128 + ((c ^ (r & 7)) << 4);
        CP_ASYNC16(dst, src);
    }
}

// Tile decode: b<1024 -> right half (bx=b>>5, ct=32+(b&31)); else triangular.
__device__ __forceinline__ void decode_tile(int b, int& bx, int& ct, bool& sym) {
    if (b < 1024) {
        bx = b >> 5; ct = 32 + (b & 31); sym = false;
    } else {
        const int t = b - 1024;
        int e = (int)((sqrtf(8.0f * t + 1.0f) - 1.0f) * 0.5f);
        while ((e + 1) * (e + 2) / 2 <= t) e++;
        while (e * (e + 1) / 2 > t) e--;
        bx = e; ct = t - e * (e + 1) / 2; sym = (ct != bx);
    }
}

// ---------------------------------------------------------------------------
// Kernel 2: persistent INT8-IMMA fused sim-GEMM + dequant + exp + row/col
// sums. R7 pipeline verbatim (STATIC schedule, 2-stage, 2 syncs/chunk,
// cross-tile prefetch); NKT=2 chunks of BK=128 int8; 4 k32 IMMA steps/chunk.
// ---------------------------------------------------------------------------
__global__ void __launch_bounds__(256, 2) simsum_mma_kernel() {
    extern __shared__ char smem[];
    const uint32_t smem_u32 = smem_to_u32(smem);
    const int tid = threadIdx.x;

    const int lane  = tid & 31;
    const int w     = tid >> 5;
    const int warpM = w >> 1;
    const int warpN = w & 1;

    const int aRow  = warpM * 32 + (lane & 7) + ((lane >> 3) & 1) * 8;
    const int aCh   = (lane >> 4) & 1;
    const int aRm   = aRow & 7;
    const int bRow  = warpN * 64 + (lane & 7) + ((lane >> 4) & 1) * 8;
    const int bCh   = (lane >> 3) & 1;
    const int bRm   = bRow & 7;
    const int aRowByte[2] = {aRow * 128, (aRow + 16) * 128};
    const int bRowByte[4] = {bRow * 128, (bRow + 16) * 128,
                             (bRow + 32) * 128, (bRow + 48) * 128};

    float* rowScratch = reinterpret_cast<float*>(smem + SCRATCH_OFF);        // [2][128]
    float* colScratch = reinterpret_cast<float*>(smem + SCRATCH_OFF) + 256;  // [2][4][64]

    int tile = blockIdx.x;
    int bx, colTile; bool sym;
    decode_tile(tile, bx, colTile, sym);
    int rowBase = bx * BM, colBase = colTile * BN;

    int chunk = 0;
    load_stage(smem_u32, 0, rowBase, colBase, tid);
    CP_COMMIT();

    #pragma unroll 1
    while (true) {
        const int nxtTile = tile + GRID_GEMM;
        const bool hasNext = (nxtTile < NTILES);
        int nbx = 0, nct = 0; bool nsym = false;
        if (hasNext) decode_tile(nxtTile, nbx, nct, nsym);
        const int nRowBase = nbx * BM, nColBase = nct * BN;

        int acc[2][8][4];
        #pragma unroll
        for (int mt = 0; mt < 2; mt++)
            #pragma unroll
            for (int nt = 0; nt < 8; nt++)
                #pragma unroll
                for (int r = 0; r < 4; r++) acc[mt][nt][r] = 0;

        #pragma unroll 1
        for (int kt = 0; kt < NKT; kt++) {
            const uint32_t stage  = smem_u32 + (uint32_t)(chunk & 1) * STAGE_BYTES;
            const uint32_t nstage = smem_u32 + (uint32_t)((chunk + 1) & 1) * STAGE_BYTES;
            if (kt + 1 < NKT) {
                load_stage(nstage, kt + 1, rowBase, colBase, tid);
                CP_COMMIT(); CP_WAIT(1);
            } else if (hasNext) {
                load_stage(nstage, 0, nRowBase, nColBase, tid);
                CP_COMMIT(); CP_WAIT(1);
            } else {
                CP_WAIT(0);
            }
            __syncthreads();

            const uint32_t bBase = stage + 16384;
            #pragma unroll
            for (int s = 0; s < 4; s++) {
                uint32_t ah[2][4], bh[4][4];
                #pragma unroll
                for (int mt = 0; mt < 2; mt++)
                    ldsm4(ah[mt], swadr(stage, aRowByte[mt], aRm, 2 * s + aCh));
                #pragma unroll
                for (int p = 0; p < 4; p++)
                    ldsm4(bh[p], swadr(bBase, bRowByte[p], bRm, 2 * s + bCh));
                #pragma unroll
                for (int mt = 0; mt < 2; mt++)
                    #pragma unroll
                    for (int nt = 0; nt < 8; nt++)
                        imma16832(acc[mt][nt], ah[mt], bh[nt >> 1][(nt & 1) * 2],
                                  bh[nt >> 1][(nt & 1) * 2 + 1]);
            }
            __syncthreads();
            chunk++;
        }

        // ---------------- Epilogue (next tile's kt0 load is in flight) -------
        // Dequant: sim = acc * ra[row] * rb[col];  e = 2^(sim * l2T)
        const float l2T = c_l2T;
        const int r8 = lane >> 2;
        float raL[4];                                  // [mt*2 + (0:row, 1:row+8)] * l2T
        #pragma unroll
        for (int mt = 0; mt < 2; mt++) {
            raL[mt * 2 + 0] = g_rs[rowBase + warpM * 32 + mt * 16 + 0 + r8] * l2T;
            raL[mt * 2 + 1] = g_rs[rowBase + warpM * 32 + mt * 16 + 8 + r8] * l2T;
        }
        float rbv[16];
        #pragma unroll
        for (int nt = 0; nt < 8; nt++) {
            const int c0 = colBase + warpN * 64 + nt * 8 + (lane & 3) * 2;
            rbv[nt * 2 + 0] = g_rs[c0];
            rbv[nt * 2 + 1] = g_rs[c0 + 1];
        }

        float rs0[2] = {0.0f, 0.0f}, rs1[2] = {0.0f, 0.0f};
        float cs[16];
        #pragma unroll
        for (int i = 0; i < 16; i++) cs[i] = 0.0f;

        #pragma unroll
        for (int mt = 0; mt < 2; mt++)
            #pragma unroll
            for (int nt = 0; nt < 8; nt++) {
                const float f0 = __int2float_rn(acc[mt][nt][0]);
                const float f1 = __int2float_rn(acc[mt][nt][1]);
                const float f2 = __int2float_rn(acc[mt][nt][2]);
                const float f3 = __int2float_rn(acc[mt][nt][3]);
                const float e0 = ex2(f0 * raL[mt * 2 + 0] * rbv[nt * 2 + 0]);
                const float e1 = ex2(f1 * raL[mt * 2 + 0] * rbv[nt * 2 + 1]);
                const float e2 = ex2(f2 * raL[mt * 2 + 1] * rbv[nt * 2 + 0]);
                const float e3 = ex2(f3 * raL[mt * 2 + 1] * rbv[nt * 2 + 1]);
                rs0[mt] += e0 + e1;
                rs1[mt] += e2 + e3;
                cs[nt * 2 + 0] += e0 + e2;
                cs[nt * 2 + 1] += e1 + e3;
            }

        #pragma unroll
        for (int off = 1; off <= 2; off <<= 1) {
            #pragma unroll
            for (int mt = 0; mt < 2; mt++) {
                rs0[mt] += __shfl_xor_sync(0xffffffffu, rs0[mt], off);
                rs1[mt] += __shfl_xor_sync(0xffffffffu, rs1[mt], off);
            }
        }
        if ((lane & 3) == 0) {
            #pragma unroll
            for (int mt = 0; mt < 2; mt++) {
                rowScratch[warpN * 128 + warpM * 32 + mt * 16 + 0 + r8] = rs0[mt];
                rowScratch[warpN * 128 + warpM * 32 + mt * 16 + 8 + r8] = rs1[mt];
            }
        }
        if (sym) {
            #pragma unroll
            for (int i = 0; i < 16; i++) {
                #pragma unroll
                for (int off = 4; off <= 16; off <<= 1)
                    cs[i] += __shfl_xor_sync(0xffffffffu, cs[i], off);
            }
            if (lane < 4) {
                #pragma unroll
                for (int nt = 0; nt < 8; nt++) {
                    colScratch[(warpN * 4 + warpM) * 64 + nt * 8 + lane * 2 + 0] = cs[nt * 2 + 0];
                    colScratch[(warpN * 4 + warpM) * 64 + nt * 8 + lane * 2 + 1] = cs[nt * 2 + 1];
                }
            }
        }
        __syncthreads();

        if (tid < 128) {
            const float p = rowScratch[tid] + rowScratch[128 + tid];
            g_partial[(size_t)(rowBase + tid) * NCOLTILES + colTile] = p;
            if (sym) {
                const int wn = tid >> 6, ix = tid & 63;
                float c = colScratch[(wn * 4 + 0) * 64 + ix] + colScratch[(wn * 4 + 1) * 64 + ix]
                        + colScratch[(wn * 4 + 2) * 64 + ix] + colScratch[(wn * 4 + 3) * 64 + ix];
                g_partial[(size_t)(colBase + tid) * NCOLTILES + bx] = c;
            }
        }
        __syncthreads();   // scratch reuse safety for next tile

        if (!hasNext) break;
        tile = nxtTile; bx = nbx; colTile = nct; sym = nsym;
        rowBase = nRowBase; colBase = nColBase;
    }
}

// ---------------------------------------------------------------------------
// Kernel 3: per-row loss + grid-wide mean (last-block pattern, deterministic).
// All correction dots via dp4a on the SAME int8 data the GEMM consumed:
//   dp  = z1n_i . z2n_i      (positive)
//   d0  = z1n_i . z2n_0      (excluded column n)
//   dii = z1n_i . z1n_i      (self-similarity; replaced by exact exp(1/T))
// loss_i = log(total - exp(d0/T) - exp(dii/T) + exp(1/T)) - dp/T
// ---------------------------------------------------------------------------
__global__ void __launch_bounds__(256) loss_reduce_kernel(float* __restrict__ out) {
    __shared__ float warpLoss[8];
    __shared__ int   isLast;
    const int bid  = blockIdx.x;
    const int row  = bid * 8 + (threadIdx.x >> 5);
    const int lane = threadIdx.x & 31;

    float total = g_partial[(size_t)row * NCOLTILES + lane]
                + g_partial[(size_t)row * NCOLTILES + lane + 32];

    const uint2 qa = reinterpret_cast<const uint2*>(g_q + (size_t)row * D)[lane];
    const uint2 qb = reinterpret_cast<const uint2*>(g_q + (size_t)(N_ROWS + row) * D)[lane];
    const uint2 qc = reinterpret_cast<const uint2*>(g_q + (size_t)N_ROWS * D)[lane];

    int dpi = __dp4a((int)qa.x, (int)qb.x, 0); dpi = __dp4a((int)qa.y, (int)qb.y, dpi);
    int d0i = __dp4a((int)qa.x, (int)qc.x, 0); d0i = __dp4a((int)qa.y, (int)qc.y, d0i);
    int dii = __dp4a((int)qa.x, (int)qa.x, 0); dii = __dp4a((int)qa.y, (int)qa.y, dii);

    #pragma unroll
    for (int off = 16; off > 0; off >>= 1) {
        total += __shfl_xor_sync(0xffffffffu, total, off);
        dpi   += __shfl_xor_sync(0xffffffffu, dpi, off);
        d0i   += __shfl_xor_sync(0xffffffffu, d0i, off);
        dii   += __shfl_xor_sync(0xffffffffu, dii, off);
    }
    if (lane == 0) {
        const float ra = g_rs[row];
        const float rb = g_rs[N_ROWS + row];
        const float rc = g_rs[N_ROWS];
        const float dp    = __int2float_rn(dpi) * ra * rb;
        const float d0    = __int2float_rn(d0i) * ra * rc;
        const float dii_f = __int2float_rn(dii) * ra * ra;
        float sum_negs = total - ex2(d0 * c_l2T) - ex2(dii_f * c_l2T) + ex2(c_l2T);
        warpLoss[threadIdx.x >> 5] = logf(sum_negs) - dp * c_invT;
    }
    __syncthreads();

    if (threadIdx.x == 0) {
        float bs = 0.0f;
        #pragma unroll
        for (int i = 0; i < 8; i++) bs += warpLoss[i];
        g_blocksum[bid] = bs;
        __threadfence();
        int old = atomicAdd(&g_counter, 1);
        isLast = (old == NLOSSBLK - 1);
    }
    __syncthreads();

    if (isLast) {
        __shared__ float s[256];
        float v = 0.0f;
        #pragma unroll
        for (int h = 0; h < 2; h++) {
            float t;
            asm volatile("ld.global.cg.f32 %0, [%1];" : "=f"(t)
                         : "l"(g_blocksum + threadIdx.x + h * 256));
            v += t;
        }
        s[threadIdx.x] = v;
        __syncthreads();
        #pragma unroll
        for (int stride = 128; stride > 0; stride >>= 1) {
            if (threadIdx.x < stride) s[threadIdx.x] += s[threadIdx.x + stride];
            __syncthreads();
        }
        if (threadIdx.x == 0) {
            out[0] = s[0] * (1.0f / N_ROWS);
            g_counter = 0;   // reset for graph replay
        }
    }
}

// ---------------------------------------------------------------------------
extern "C" void kernel_launch(void* const* d_in, const int* in_sizes, int n_in,
                              void* d_out, int out_size) {
    const float* z1 = (const float*)d_in[0];
    const float* z2 = (const float*)d_in[1];
    float* out = (float*)d_out;

    cudaFuncSetAttribute(simsum_mma_kernel,
                         cudaFuncAttributeMaxDynamicSharedMemorySize, SMEM_TOTAL);

    normalize_kernel<<<TWO_N / 8, 256>>>(z1, z2);
    simsum_mma_kernel<<<GRID_GEMM, 256, SMEM_TOTAL>>>();
    loss_reduce_kernel<<<NLOSSBLK, 256>>>(out);
}